// round 12
// baseline (speedup 1.0000x reference)
#include <cuda_runtime.h>
#include <math.h>

#define HH 512
#define WW 1024
#define BATCH 4
#define BW 32
#define TH 8     // pixel tile height per block
#define TY 4     // thread rows (2 pixels each)

typedef unsigned long long ull;

// ---------------- packed f32x2 primitives (sm_103a) ----------------
__device__ __forceinline__ ull pack2(float lo, float hi) {
    ull v;
    asm("mov.b64 %0, {%1, %2};" : "=l"(v)
        : "r"(__float_as_uint(lo)), "r"(__float_as_uint(hi)));
    return v;
}
__device__ __forceinline__ void unpack2(ull v, float& lo, float& hi) {
    unsigned a, b;
    asm("mov.b64 {%0, %1}, %2;" : "=r"(a), "=r"(b) : "l"(v));
    lo = __uint_as_float(a);
    hi = __uint_as_float(b);
}
// (a.lo, b.lo)
__device__ __forceinline__ ull pack_ll(ull a, ull b) {
    ull r;
    asm("{\n\t"
        ".reg .b32 al, ah, bl, bh;\n\t"
        "mov.b64 {al, ah}, %1;\n\t"
        "mov.b64 {bl, bh}, %2;\n\t"
        "mov.b64 %0, {al, bl};\n\t"
        "}" : "=l"(r) : "l"(a), "l"(b));
    return r;
}
// (a.lo, b.hi)
__device__ __forceinline__ ull pack_lh(ull a, ull b) {
    ull r;
    asm("{\n\t"
        ".reg .b32 al, ah, bl, bh;\n\t"
        "mov.b64 {al, ah}, %1;\n\t"
        "mov.b64 {bl, bh}, %2;\n\t"
        "mov.b64 %0, {al, bh};\n\t"
        "}" : "=l"(r) : "l"(a), "l"(b));
    return r;
}
__device__ __forceinline__ float lane0(ull a) {
    unsigned x, y;
    asm("mov.b64 {%0, %1}, %2;" : "=r"(x), "=r"(y) : "l"(a));
    return __uint_as_float(x);
}
__device__ __forceinline__ ull add2(ull a, ull b) {
    ull d; asm("add.rn.f32x2 %0, %1, %2;" : "=l"(d) : "l"(a), "l"(b)); return d;
}
__device__ __forceinline__ ull sub2(ull a, ull b) {
    ull d; asm("sub.rn.f32x2 %0, %1, %2;" : "=l"(d) : "l"(a), "l"(b)); return d;
}
__device__ __forceinline__ ull mul2(ull a, ull b) {
    ull d; asm("mul.rn.f32x2 %0, %1, %2;" : "=l"(d) : "l"(a), "l"(b)); return d;
}
__device__ __forceinline__ ull fma2(ull a, ull b, ull c) {
    ull d; asm("fma.rn.f32x2 %0, %1, %2, %3;" : "=l"(d) : "l"(a), "l"(b), "l"(c)); return d;
}
__device__ __forceinline__ ull neg2(ull a) { return a ^ 0x8000000080000000ULL; }

struct dd2 { ull hi, lo; };

// sum of 3 packed products, exact per lane (TwoProd + TwoSum chain)
__device__ __forceinline__ dd2 sum3prod2(ull a0, ull b0, ull a1, ull b1,
                                         ull a2, ull b2) {
    ull p0 = mul2(a0, b0), e0 = fma2(a0, b0, neg2(p0));
    ull p1 = mul2(a1, b1), e1 = fma2(a1, b1, neg2(p1));
    ull p2 = mul2(a2, b2), e2 = fma2(a2, b2, neg2(p2));
    ull s  = add2(p0, p1);
    ull bb = sub2(s, p0);
    ull er1 = add2(sub2(p0, sub2(s, bb)), sub2(p1, bb));
    ull s2  = add2(s, p2);
    ull bb2 = sub2(s2, s);
    ull er2 = add2(sub2(s, sub2(s2, bb2)), sub2(p2, bb2));
    dd2 r;
    r.hi = s2;
    r.lo = add2(add2(add2(e0, e1), e2), add2(er1, er2));
    return r;
}
// exact packed dd + dd
__device__ __forceinline__ dd2 ddadd2(dd2 a, dd2 b) {
    ull s  = add2(a.hi, b.hi);
    ull bb = sub2(s, a.hi);
    ull er = add2(sub2(a.hi, sub2(s, bb)), sub2(b.hi, bb));
    dd2 r; r.hi = s; r.lo = add2(add2(a.lo, b.lo), er);
    return r;
}
// dd += packed plain value, exact
__device__ __forceinline__ dd2 ddaddf2(dd2 a, ull p) {
    ull s  = add2(a.hi, p);
    ull bb = sub2(s, a.hi);
    ull er = add2(sub2(a.hi, sub2(s, bb)), sub2(p, bb));
    dd2 r; r.hi = s; r.lo = add2(a.lo, er);
    return r;
}
// relaxed packed dd multiply (drops lo*lo)
__device__ __forceinline__ dd2 ddmul2(dd2 a, dd2 b) {
    ull p = mul2(a.hi, b.hi);
    ull e = fma2(a.hi, b.hi, neg2(p));
    e = fma2(a.hi, b.lo, e);
    e = fma2(a.lo, b.hi, e);
    dd2 r; r.hi = p; r.lo = e;
    return r;
}
// packed dd * packed plain
__device__ __forceinline__ dd2 ddmulf2(dd2 a, ull b) {
    ull p = mul2(a.hi, b);
    ull e = fma2(a.hi, b, neg2(p));
    e = fma2(a.lo, b, e);
    dd2 r; r.hi = p; r.lo = e;
    return r;
}
// packed cofactor a*b - c*d, exact hi-difference
__device__ __forceinline__ dd2 ddcof2(dd2 a, dd2 b, dd2 c, dd2 d) {
    dd2 p = ddmul2(a, b);
    dd2 q = ddmul2(c, d);
    ull s  = sub2(p.hi, q.hi);
    ull bb = sub2(s, p.hi);
    ull er = add2(sub2(p.hi, sub2(s, bb)), sub2(neg2(q.hi), bb));
    dd2 r; r.hi = s; r.lo = add2(er, sub2(p.lo, q.lo));
    return r;
}
// exact packed 3-sum of dd values
__device__ __forceinline__ dd2 sum3dd2(dd2 a, dd2 b, dd2 c) {
    ull s  = add2(a.hi, b.hi);
    ull bb = sub2(s, a.hi);
    ull er1 = add2(sub2(a.hi, sub2(s, bb)), sub2(b.hi, bb));
    ull s2  = add2(s, c.hi);
    ull bb2 = sub2(s2, s);
    ull er2 = add2(sub2(s, sub2(s2, bb2)), sub2(c.hi, bb2));
    dd2 r;
    r.hi = s2;
    r.lo = add2(add2(add2(a.lo, b.lo), c.lo), add2(er1, er2));
    return r;
}

// ---------------- ray tables (sin/cos in double, rounded to fp32) ----------
__device__ float g_st[WW];
__device__ float g_ct[WW];
__device__ float g_sp[HH];
__device__ float g_cp[HH];

__global__ void rays_kernel() {
    int t = blockIdx.x * blockDim.x + threadIdx.x;
    const float PI_F = 3.14159265358979323846f;   // fl32(pi)
    if (t < WW) {
        float jn = __fmul_rn((float)t + 0.5f, 1.0f / (float)WW);
        float th = __fsub_rn(__fmul_rn(jn, __fmul_rn(2.0f, PI_F)), PI_F);
        double thd = (double)th;
        g_st[t] = (float)sin(thd);
        g_ct[t] = (float)cos(thd);
    } else if (t < WW + HH) {
        int i = t - WW;
        float in_ = __fmul_rn((float)i + 0.5f, 1.0f / (float)HH);
        float ph = __fsub_rn(0.5f * PI_F, __fmul_rn(in_, PI_F));
        double phd = (double)ph;
        g_sp[i] = (float)sin(phd);
        g_cp[i] = (float)cos(phd);
    }
}

// Phase B pipelines (natural packing): H0=(xx,yy) H1=(zz,xy) H2=(xz,yz);
// b = (x,y) packed plain + z plain. Phase C repacks lanes as pixel pairs.
__global__ __launch_bounds__(BW * TY, 9)
void normals_kernel(const float* __restrict__ depth, float* __restrict__ out) {
    __shared__ ull Pxy[TH + 2][BW + 2];         // (x, y) per point
    __shared__ ull Pzz[TH + 2][BW + 2];         // (z, z) per point
    __shared__ ulonglong2 HsP[3][TH + 2][BW];   // dd {hi2, lo2} pipelines
    __shared__ ull HsB[TH + 2][BW];             // packed (x,y) plain sums
    __shared__ float HsZ[TH + 2][BW];           // plain z sums

    const int bb = blockIdx.z;
    const int i0 = blockIdx.y * TH;
    const int j0 = blockIdx.x * BW;
    const int tid = threadIdx.y * BW + threadIdx.x;
    const int NT = BW * TY;
    const float* dptr = depth + (size_t)bb * (HH * WW);

    // Phase A: (TH+2)x(BW+2) tile of fp32 3D points, zero-padded, stored as
    // natural packs (x,y) and (z,z).
    for (int t = tid; t < (TH + 2) * (BW + 2); t += NT) {
        int ly = t / (BW + 2);
        int lx = t - ly * (BW + 2);
        int gi = i0 + ly - 1;
        int gj = j0 + lx - 1;
        float px = 0.0f, py = 0.0f, pz = 0.0f;
        if (gi >= 0 && gi < HH && gj >= 0 && gj < WW) {
            float d  = __ldg(&dptr[(size_t)gi * WW + gj]);
            float st = g_st[gj];
            float ct = g_ct[gj];
            float sp = g_sp[gi];
            float cp = g_cp[gi];
            float x = __fmul_rn(cp, st);
            float z = __fmul_rn(cp, ct);
            px = __fmul_rn(d, x);
            py = __fmul_rn(d, sp);
            pz = __fmul_rn(d, z);
        }
        Pxy[ly][lx] = pack2(px, py);
        Pzz[ly][lx] = pack2(pz, pz);
    }
    __syncthreads();

    // Phase B: exact horizontal 3-window sums; operands are natural 64-bit
    // loads, only (z,x)/(z,y) need a cross-half combine.
    for (int t = tid; t < (TH + 2) * BW; t += NT) {
        int ly = t / BW;
        int lx = t - ly * BW;
        ull xy0 = Pxy[ly][lx], xy1 = Pxy[ly][lx + 1], xy2 = Pxy[ly][lx + 2];
        ull zz0 = Pzz[ly][lx], zz1 = Pzz[ly][lx + 1], zz2 = Pzz[ly][lx + 2];

        ull zx0 = pack_ll(zz0, xy0), zy0 = pack_lh(zz0, xy0);
        ull zx1 = pack_ll(zz1, xy1), zy1 = pack_lh(zz1, xy1);
        ull zx2 = pack_ll(zz2, xy2), zy2 = pack_lh(zz2, xy2);

        dd2 H0 = sum3prod2(xy0, xy0, xy1, xy1, xy2, xy2);  // (xx, yy)
        dd2 H1 = sum3prod2(zx0, zy0, zx1, zy1, zx2, zy2);  // (zz, xy)
        dd2 H2 = sum3prod2(xy0, zz0, xy1, zz1, xy2, zz2);  // (xz, yz)

        HsP[0][ly][lx] = make_ulonglong2(H0.hi, H0.lo);
        HsP[1][ly][lx] = make_ulonglong2(H1.hi, H1.lo);
        HsP[2][ly][lx] = make_ulonglong2(H2.hi, H2.lo);
        HsB[ly][lx] = add2(add2(xy0, xy1), xy2);           // (x, y)
        float z0 = lane0(zz0), z1 = lane0(zz1), z2 = lane0(zz2);
        HsZ[ly][lx] = __fadd_rn(__fadd_rn(z0, z1), z2);    // z
    }
    __syncthreads();

    // Phase C1: vertical sums for TWO adjacent pixels per thread, sharing the
    // middle partial t = h[r] + h[r+1].
    const int ty = threadIdx.y;
    const int tx = threadIdx.x;
    const int r0 = 2 * ty;

    dd2 Vp0[3], Vp1[3];
#pragma unroll
    for (int q = 0; q < 3; q++) {
        ulonglong2 h0 = HsP[q][r0][tx];
        ulonglong2 h1 = HsP[q][r0 + 1][tx];
        ulonglong2 h2 = HsP[q][r0 + 2][tx];
        ulonglong2 h3 = HsP[q][r0 + 3][tx];
        dd2 a; a.hi = h0.x; a.lo = h0.y;
        dd2 b; b.hi = h1.x; b.lo = h1.y;
        dd2 c; c.hi = h2.x; c.lo = h2.y;
        dd2 d; d.hi = h3.x; d.lo = h3.y;
        dd2 t = ddadd2(b, c);
        Vp0[q] = ddadd2(t, a);
        Vp1[q] = ddadd2(t, d);
    }
    ull  B0 = HsB[r0][tx], B1 = HsB[r0 + 1][tx];
    ull  B2 = HsB[r0 + 2][tx], B3 = HsB[r0 + 3][tx];
    ull  tB = add2(B1, B2);
    ull  vb0 = add2(tB, B0);
    ull  vb1 = add2(tB, B3);
    float z0 = HsZ[r0][tx], z1 = HsZ[r0 + 1][tx];
    float z2 = HsZ[r0 + 2][tx], z3 = HsZ[r0 + 3][tx];
    float tZ = __fadd_rn(z1, z2);
    float vz0 = __fadd_rn(tZ, z0);
    float vz1 = __fadd_rn(tZ, z3);

    // Lane conversion: quantity-packed -> pixel-packed.
    // Vp[0]=(xx,yy) Vp[1]=(zz,xy) Vp[2]=(xz,yz)
    float xx0, yy0, xx0l, yy0l; unpack2(Vp0[0].hi, xx0, yy0); unpack2(Vp0[0].lo, xx0l, yy0l);
    float zz0q, xy0q, zz0l, xy0l; unpack2(Vp0[1].hi, zz0q, xy0q); unpack2(Vp0[1].lo, zz0l, xy0l);
    float xz0, yz0, xz0l, yz0l; unpack2(Vp0[2].hi, xz0, yz0); unpack2(Vp0[2].lo, xz0l, yz0l);
    float xx1, yy1, xx1l, yy1l; unpack2(Vp1[0].hi, xx1, yy1); unpack2(Vp1[0].lo, xx1l, yy1l);
    float zz1q, xy1q, zz1l, xy1l; unpack2(Vp1[1].hi, zz1q, xy1q); unpack2(Vp1[1].lo, zz1l, xy1l);
    float xz1, yz1, xz1l, yz1l; unpack2(Vp1[2].hi, xz1, yz1); unpack2(Vp1[2].lo, xz1l, yz1l);
    float bx0, by0; unpack2(vb0, bx0, by0);
    float bx1, by1; unpack2(vb1, bx1, by1);

    dd2 Ga; Ga.hi = pack2(xx0, xx1);   Ga.lo = pack2(xx0l, xx1l);
    dd2 Gb; Gb.hi = pack2(xy0q, xy1q); Gb.lo = pack2(xy0l, xy1l);
    dd2 Gc; Gc.hi = pack2(xz0, xz1);   Gc.lo = pack2(xz0l, xz1l);
    dd2 Gd; Gd.hi = pack2(yy0, yy1);   Gd.lo = pack2(yy0l, yy1l);
    dd2 Ge; Ge.hi = pack2(yz0, yz1);   Ge.lo = pack2(yz0l, yz1l);
    dd2 Gf; Gf.hi = pack2(zz0q, zz1q); Gf.lo = pack2(zz0l, zz1l);
    ull Bx = pack2(bx0, bx1);
    ull By = pack2(by0, by1);
    ull Bz = pack2(vz0, vz1);

    const ull EPS2 = pack2(1e-5f, 1e-5f);
    Ga = ddaddf2(Ga, EPS2);
    Gd = ddaddf2(Gd, EPS2);
    Gf = ddaddf2(Gf, EPS2);

    // Phase C2: packed symmetric adjugate solve (both pixels per instruction).
    dd2 A00 = ddcof2(Gd, Gf, Ge, Ge);
    dd2 A01 = ddcof2(Gc, Ge, Gb, Gf);
    dd2 A02 = ddcof2(Gb, Ge, Gc, Gd);
    dd2 A11 = ddcof2(Ga, Gf, Gc, Gc);
    dd2 A12 = ddcof2(Gb, Gc, Ga, Ge);
    dd2 A22 = ddcof2(Ga, Gd, Gb, Gb);

    dd2 md0 = sum3dd2(ddmulf2(A00, Bx), ddmulf2(A01, By), ddmulf2(A02, Bz));
    dd2 md1 = sum3dd2(ddmulf2(A01, Bx), ddmulf2(A11, By), ddmulf2(A12, Bz));
    dd2 md2 = sum3dd2(ddmulf2(A02, Bx), ddmulf2(A12, By), ddmulf2(A22, Bz));

    ull m0p = add2(md0.hi, md0.lo);
    ull m1p = add2(md1.hi, md1.lo);
    ull m2p = add2(md2.hi, md2.lo);

    ull nnp = mul2(m0p, m0p);
    nnp = fma2(m1p, m1p, nnp);
    nnp = fma2(m2p, m2p, nnp);

    float m0_0, m0_1; unpack2(m0p, m0_0, m0_1);
    float m1_0, m1_1; unpack2(m1p, m1_0, m1_1);
    float m2_0, m2_1; unpack2(m2p, m2_0, m2_1);
    float nn0, nn1;   unpack2(nnp, nn0, nn1);

    float norm0 = sqrtf(nn0); if (norm0 == 0.0f) norm0 = 1e-4f;
    float norm1 = sqrtf(nn1); if (norm1 == 0.0f) norm1 = 1e-4f;

    const int gi = i0 + 2 * ty;
    const int gj = j0 + tx;
    size_t base = (size_t)bb * 3 * (HH * WW) + (size_t)gi * WW + gj;
    out[base]               = __fdiv_rn(-m0_0, norm0);
    out[base +     HH * WW] = __fdiv_rn(-m1_0, norm0);
    out[base + 2 * HH * WW] = __fdiv_rn(-m2_0, norm0);
    base += WW;   // next row, pixel 1
    out[base]               = __fdiv_rn(-m0_1, norm1);
    out[base +     HH * WW] = __fdiv_rn(-m1_1, norm1);
    out[base + 2 * HH * WW] = __fdiv_rn(-m2_1, norm1);
}

extern "C" void kernel_launch(void* const* d_in, const int* in_sizes, int n_in,
                              void* d_out, int out_size) {
    const float* depth = (const float*)d_in[0];
    float* out = (float*)d_out;

    rays_kernel<<<(WW + HH + 255) / 256, 256>>>();

    dim3 block(BW, TY, 1);
    dim3 grid(WW / BW, HH / TH, BATCH);
    normals_kernel<<<grid, block>>>(depth, out);
}

// round 13
// speedup vs baseline: 1.4673x; 1.4673x over previous
#include <cuda_runtime.h>
#include <math.h>

#define HH 512
#define WW 1024
#define BATCH 4
#define BW 16
#define TH 16

// ---------------- ray tables (sin/cos in double, rounded to fp32) ----------
__device__ float g_st[WW];
__device__ float g_ct[WW];
__device__ float g_sp[HH];
__device__ float g_cp[HH];

__global__ void rays_kernel() {
    int t = blockIdx.x * blockDim.x + threadIdx.x;
    const float PI_F = 3.14159265358979323846f;   // fl32(pi)
    if (t < WW) {
        float jn = __fmul_rn((float)t + 0.5f, 1.0f / (float)WW);
        float th = __fsub_rn(__fmul_rn(jn, __fmul_rn(2.0f, PI_F)), PI_F);
        double thd = (double)th;
        g_st[t] = (float)sin(thd);
        g_ct[t] = (float)cos(thd);
    } else if (t < WW + HH) {
        int i = t - WW;
        float in_ = __fmul_rn((float)i + 0.5f, 1.0f / (float)HH);
        float ph = __fsub_rn(0.5f * PI_F, __fmul_rn(in_, PI_F));
        double phd = (double)ph;
        g_sp[i] = (float)sin(phd);
        g_cp[i] = (float)cos(phd);
    }
}

// Kahan-compensated 2x2 determinant: a*b - c*d to ~1.5 ulp of the RESULT
__device__ __forceinline__ float det2(float a, float b, float c, float d) {
    float p = __fmul_rn(a, b);
    float e = fmaf(a, b, -p);
    float q = __fmul_rn(c, d);
    float f = fmaf(c, d, -q);
    return __fadd_rn(__fsub_rn(p, q), __fsub_rn(e, f));
}
// compensated a*x + b*y + c*z (guards the heavy cancellation in adj*b)
__device__ __forceinline__ float dot3c(float a, float x, float b, float y,
                                       float c, float z) {
    float p0 = __fmul_rn(a, x), e0 = fmaf(a, x, -p0);
    float p1 = __fmul_rn(b, y), e1 = fmaf(b, y, -p1);
    float p2 = __fmul_rn(c, z), e2 = fmaf(c, z, -p2);
    float s  = __fadd_rn(p0, p1);
    float t  = __fsub_rn(s, p0);
    float er1 = __fadd_rn(__fsub_rn(p0, __fsub_rn(s, t)), __fsub_rn(p1, t));
    float s2 = __fadd_rn(s, p2);
    float t2 = __fsub_rn(s2, s);
    float er2 = __fadd_rn(__fsub_rn(s, __fsub_rn(s2, t2)), __fsub_rn(p2, t2));
    float lo = __fadd_rn(__fadd_rn(er1, er2), __fadd_rn(__fadd_rn(e0, e1), e2));
    return __fadd_rn(s2, lo);
}

__global__ __launch_bounds__(256)
void normals_kernel(const float* __restrict__ depth, float* __restrict__ out) {
    __shared__ float4 pts[TH + 2][BW + 2];  // rotated-frame points
    __shared__ float4 H1[TH + 2][BW];       // xx, xy, xz, yy
    __shared__ float4 H2[TH + 2][BW];       // yz, zz, bx, by
    __shared__ float  H3[TH + 2][BW];       // bz

    const int bb = blockIdx.z;
    const int i0 = blockIdx.y * TH;
    const int j0 = blockIdx.x * BW;
    const int tid = threadIdx.y * BW + threadIdx.x;
    const float* dptr = depth + (size_t)bb * (HH * WW);

    // Per-block basis from the center pixel's ray (all threads compute the
    // same values deterministically — no sync needed).
    const int ic = i0 + TH / 2;
    const int jc = j0 + BW / 2;
    float r1x = g_cp[ic] * g_st[jc];
    float r1y = g_sp[ic];
    float r1z = g_cp[ic] * g_ct[jc];
    float ax, ay, az;
    if (fabsf(r1y) < 0.9f) { ax = 0.f; ay = 1.f; az = 0.f; }
    else                   { ax = 1.f; ay = 0.f; az = 0.f; }
    float b2x = r1y * az - r1z * ay;
    float b2y = r1z * ax - r1x * az;
    float b2z = r1x * ay - r1y * ax;
    float inv2 = rsqrtf(b2x * b2x + b2y * b2y + b2z * b2z);
    b2x *= inv2; b2y *= inv2; b2z *= inv2;
    float b3x = r1y * b2z - r1z * b2y;
    float b3y = r1z * b2x - r1x * b2z;
    float b3z = r1x * b2y - r1y * b2x;

    // Phase A: build fp32 points (reference op order), rotate into the local
    // basis, store. Padding points are exact zeros.
    for (int t = tid; t < (TH + 2) * (BW + 2); t += 256) {
        int ly = t / (BW + 2);
        int lx = t - ly * (BW + 2);
        int gi = i0 + ly - 1;
        int gj = j0 + lx - 1;
        float4 q = make_float4(0.f, 0.f, 0.f, 0.f);
        if (gi >= 0 && gi < HH && gj >= 0 && gj < WW) {
            float d  = __ldg(&dptr[(size_t)gi * WW + gj]);
            float st = g_st[gj];
            float ct = g_ct[gj];
            float sp = g_sp[gi];
            float cp = g_cp[gi];
            float px = __fmul_rn(d, __fmul_rn(cp, st));
            float py = __fmul_rn(d, sp);
            float pz = __fmul_rn(d, __fmul_rn(cp, ct));
            q.x = fmaf(r1x, px, fmaf(r1y, py, r1z * pz));  // along-ray
            q.y = fmaf(b2x, px, fmaf(b2y, py, b2z * pz));  // transverse
            q.z = fmaf(b3x, px, fmaf(b3y, py, b3z * pz));  // transverse
        }
        pts[ly][lx] = q;
    }
    __syncthreads();

    // Phase B: horizontal 3-window sums of the 9 quantities, plain fp32.
    for (int t = tid; t < (TH + 2) * BW; t += 256) {
        int ly = t / BW;
        int lx = t - ly * BW;
        float4 p0 = pts[ly][lx];
        float4 p1 = pts[ly][lx + 1];
        float4 p2 = pts[ly][lx + 2];
        float xx = fmaf(p2.x, p2.x, fmaf(p1.x, p1.x, p0.x * p0.x));
        float xy = fmaf(p2.x, p2.y, fmaf(p1.x, p1.y, p0.x * p0.y));
        float xz = fmaf(p2.x, p2.z, fmaf(p1.x, p1.z, p0.x * p0.z));
        float yy = fmaf(p2.y, p2.y, fmaf(p1.y, p1.y, p0.y * p0.y));
        float yz = fmaf(p2.y, p2.z, fmaf(p1.y, p1.z, p0.y * p0.z));
        float zz = fmaf(p2.z, p2.z, fmaf(p1.z, p1.z, p0.z * p0.z));
        float sx = __fadd_rn(__fadd_rn(p0.x, p1.x), p2.x);
        float sy = __fadd_rn(__fadd_rn(p0.y, p1.y), p2.y);
        float sz = __fadd_rn(__fadd_rn(p0.z, p1.z), p2.z);
        H1[ly][lx] = make_float4(xx, xy, xz, yy);
        H2[ly][lx] = make_float4(yz, zz, sx, sy);
        H3[ly][lx] = sz;
    }
    __syncthreads();

    // Phase C: vertical 3-sums -> G', b'; guarded fp32 adjugate solve;
    // rotate back; normalize (reference semantics).
    const int ty = threadIdx.y;
    const int tx = threadIdx.x;
    float4 u0 = H1[ty][tx], u1 = H1[ty + 1][tx], u2 = H1[ty + 2][tx];
    float4 v0 = H2[ty][tx], v1 = H2[ty + 1][tx], v2 = H2[ty + 2][tx];
    float ga = __fadd_rn(__fadd_rn(u0.x, u1.x), u2.x);
    float gb = __fadd_rn(__fadd_rn(u0.y, u1.y), u2.y);
    float gc = __fadd_rn(__fadd_rn(u0.z, u1.z), u2.z);
    float gd = __fadd_rn(__fadd_rn(u0.w, u1.w), u2.w);
    float ge = __fadd_rn(__fadd_rn(v0.x, v1.x), v2.x);
    float gf = __fadd_rn(__fadd_rn(v0.y, v1.y), v2.y);
    float bx = __fadd_rn(__fadd_rn(v0.z, v1.z), v2.z);
    float by = __fadd_rn(__fadd_rn(v0.w, v1.w), v2.w);
    float bz = __fadd_rn(__fadd_rn(H3[ty][tx], H3[ty + 1][tx]), H3[ty + 2][tx]);

    ga = __fadd_rn(ga, 1e-5f);
    gd = __fadd_rn(gd, 1e-5f);
    gf = __fadd_rn(gf, 1e-5f);

    // Symmetric adjugate with compensated 2x2 determinants.
    float A00 = det2(gd, gf, ge, ge);
    float A01 = det2(gc, ge, gb, gf);
    float A02 = det2(gb, ge, gc, gd);
    float A11 = det2(ga, gf, gc, gc);
    float A12 = det2(gb, gc, ga, ge);
    float A22 = det2(ga, gd, gb, gb);

    // m' = adj(G') b' with compensated dots (heavy cancellation here).
    float m0 = dot3c(A00, bx, A01, by, A02, bz);
    float m1 = dot3c(A01, bx, A11, by, A12, bz);
    float m2 = dot3c(A02, bx, A12, by, A22, bz);

    // Rotate back: n = B m'  (B columns = r1, b2, b3).
    float nx = fmaf(m0, r1x, fmaf(m1, b2x, m2 * b3x));
    float ny = fmaf(m0, r1y, fmaf(m1, b2y, m2 * b3y));
    float nz = fmaf(m0, r1z, fmaf(m1, b2z, m2 * b3z));

    float nn = fmaf(nx, nx, fmaf(ny, ny, nz * nz));
    float norm = sqrtf(nn);
    if (norm == 0.0f) norm = 1e-4f;
    float o0 = __fdiv_rn(-nx, norm);
    float o1 = __fdiv_rn(-ny, norm);
    float o2 = __fdiv_rn(-nz, norm);

    const int gi = i0 + ty;
    const int gj = j0 + tx;
    size_t base = (size_t)bb * 3 * (HH * WW) + (size_t)gi * WW + gj;
    out[base]               = o0;
    out[base +     HH * WW] = o1;
    out[base + 2 * HH * WW] = o2;
}

extern "C" void kernel_launch(void* const* d_in, const int* in_sizes, int n_in,
                              void* d_out, int out_size) {
    const float* depth = (const float*)d_in[0];
    float* out = (float*)d_out;

    rays_kernel<<<(WW + HH + 255) / 256, 256>>>();

    dim3 block(BW, TH, 1);
    dim3 grid(WW / BW, HH / TH, BATCH);
    normals_kernel<<<grid, block>>>(depth, out);
}

// round 14
// speedup vs baseline: 1.7347x; 1.1823x over previous
#include <cuda_runtime.h>
#include <math.h>

#define HH 512
#define WW 1024
#define BATCH 4
#define BW 16
#define TH 16
#define TY 8    // thread rows; each thread owns pixel rows 2*ty and 2*ty+1

// ---------------- ray tables (sin/cos in double, rounded to fp32) ----------
__device__ float g_st[WW];
__device__ float g_ct[WW];
__device__ float g_sp[HH];
__device__ float g_cp[HH];

__global__ void rays_kernel() {
    int t = blockIdx.x * blockDim.x + threadIdx.x;
    const float PI_F = 3.14159265358979323846f;   // fl32(pi)
    if (t < WW) {
        float jn = __fmul_rn((float)t + 0.5f, 1.0f / (float)WW);
        float th = __fsub_rn(__fmul_rn(jn, __fmul_rn(2.0f, PI_F)), PI_F);
        double thd = (double)th;
        g_st[t] = (float)sin(thd);
        g_ct[t] = (float)cos(thd);
    } else if (t < WW + HH) {
        int i = t - WW;
        float in_ = __fmul_rn((float)i + 0.5f, 1.0f / (float)HH);
        float ph = __fsub_rn(0.5f * PI_F, __fmul_rn(in_, PI_F));
        double phd = (double)ph;
        g_sp[i] = (float)sin(phd);
        g_cp[i] = (float)cos(phd);
    }
}

// Kahan-compensated 2x2 determinant: a*b - c*d
__device__ __forceinline__ float det2(float a, float b, float c, float d) {
    float p = __fmul_rn(a, b);
    float e = fmaf(a, b, -p);
    float q = __fmul_rn(c, d);
    float f = fmaf(c, d, -q);
    return __fadd_rn(__fsub_rn(p, q), __fsub_rn(e, f));
}
// compensated a*x + b*y + c*z
__device__ __forceinline__ float dot3c(float a, float x, float b, float y,
                                       float c, float z) {
    float p0 = __fmul_rn(a, x), e0 = fmaf(a, x, -p0);
    float p1 = __fmul_rn(b, y), e1 = fmaf(b, y, -p1);
    float p2 = __fmul_rn(c, z), e2 = fmaf(c, z, -p2);
    float s  = __fadd_rn(p0, p1);
    float t  = __fsub_rn(s, p0);
    float er1 = __fadd_rn(__fsub_rn(p0, __fsub_rn(s, t)), __fsub_rn(p1, t));
    float s2 = __fadd_rn(s, p2);
    float t2 = __fsub_rn(s2, s);
    float er2 = __fadd_rn(__fsub_rn(s, __fsub_rn(s2, t2)), __fsub_rn(p2, t2));
    float lo = __fadd_rn(__fadd_rn(er1, er2), __fadd_rn(__fadd_rn(e0, e1), e2));
    return __fadd_rn(s2, lo);
}

// Full per-pixel solve in the rotated frame + rotate back + normalize.
__device__ __forceinline__ void solve_pixel(
    float ga, float gb, float gc, float gd, float ge, float gf,
    float bx, float by, float bz,
    float r1x, float r1y, float r1z,
    float b2x, float b2y, float b2z,
    float b3x, float b3y, float b3z,
    float& o0, float& o1, float& o2)
{
    ga = __fadd_rn(ga, 1e-5f);
    gd = __fadd_rn(gd, 1e-5f);
    gf = __fadd_rn(gf, 1e-5f);

    float A00 = det2(gd, gf, ge, ge);
    float A01 = det2(gc, ge, gb, gf);
    float A02 = det2(gb, ge, gc, gd);
    float A11 = det2(ga, gf, gc, gc);
    float A12 = det2(gb, gc, ga, ge);
    float A22 = det2(ga, gd, gb, gb);

    float m0 = dot3c(A00, bx, A01, by, A02, bz);
    float m1 = dot3c(A01, bx, A11, by, A12, bz);
    float m2 = dot3c(A02, bx, A12, by, A22, bz);

    float nx = fmaf(m0, r1x, fmaf(m1, b2x, m2 * b3x));
    float ny = fmaf(m0, r1y, fmaf(m1, b2y, m2 * b3y));
    float nz = fmaf(m0, r1z, fmaf(m1, b2z, m2 * b3z));

    float nn = fmaf(nx, nx, fmaf(ny, ny, nz * nz));
    float norm = sqrtf(nn);
    if (norm == 0.0f) norm = 1e-4f;
    o0 = __fdiv_rn(-nx, norm);
    o1 = __fdiv_rn(-ny, norm);
    o2 = __fdiv_rn(-nz, norm);
}

__global__ __launch_bounds__(BW * TY)
void normals_kernel(const float* __restrict__ depth, float* __restrict__ out) {
    __shared__ float4 pts[TH + 2][BW + 2];  // rotated-frame points
    __shared__ float4 H1[TH + 2][BW];       // xx, xy, xz, yy
    __shared__ float4 H2[TH + 2][BW];       // yz, zz, bx, by
    __shared__ float  H3[TH + 2][BW];       // bz

    const int bb = blockIdx.z;
    const int i0 = blockIdx.y * TH;
    const int j0 = blockIdx.x * BW;
    const int tid = threadIdx.y * BW + threadIdx.x;
    const int NT = BW * TY;   // 128
    const float* dptr = depth + (size_t)bb * (HH * WW);

    // Per-block basis from the center pixel's ray (same tile geometry as R13).
    const int ic = i0 + TH / 2;
    const int jc = j0 + BW / 2;
    float r1x = g_cp[ic] * g_st[jc];
    float r1y = g_sp[ic];
    float r1z = g_cp[ic] * g_ct[jc];
    float ax, ay, az;
    if (fabsf(r1y) < 0.9f) { ax = 0.f; ay = 1.f; az = 0.f; }
    else                   { ax = 1.f; ay = 0.f; az = 0.f; }
    float b2x = r1y * az - r1z * ay;
    float b2y = r1z * ax - r1x * az;
    float b2z = r1x * ay - r1y * ax;
    float inv2 = rsqrtf(b2x * b2x + b2y * b2y + b2z * b2z);
    b2x *= inv2; b2y *= inv2; b2z *= inv2;
    float b3x = r1y * b2z - r1z * b2y;
    float b3y = r1z * b2x - r1x * b2z;
    float b3z = r1x * b2y - r1y * b2x;

    // Phase A: rotated fp32 point tile, zero-padded.
#pragma unroll
    for (int t = tid; t < (TH + 2) * (BW + 2); t += NT) {
        int ly = t / (BW + 2);
        int lx = t - ly * (BW + 2);
        int gi = i0 + ly - 1;
        int gj = j0 + lx - 1;
        float4 q = make_float4(0.f, 0.f, 0.f, 0.f);
        if (gi >= 0 && gi < HH && gj >= 0 && gj < WW) {
            float d  = __ldg(&dptr[(size_t)gi * WW + gj]);
            float st = g_st[gj];
            float ct = g_ct[gj];
            float sp = g_sp[gi];
            float cp = g_cp[gi];
            float px = __fmul_rn(d, __fmul_rn(cp, st));
            float py = __fmul_rn(d, sp);
            float pz = __fmul_rn(d, __fmul_rn(cp, ct));
            q.x = fmaf(r1x, px, fmaf(r1y, py, r1z * pz));
            q.y = fmaf(b2x, px, fmaf(b2y, py, b2z * pz));
            q.z = fmaf(b3x, px, fmaf(b3y, py, b3z * pz));
        }
        pts[ly][lx] = q;
    }
    __syncthreads();

    // Phase B: horizontal 3-window sums, plain fp32 (identical to R13).
#pragma unroll
    for (int t = tid; t < (TH + 2) * BW; t += NT) {
        int ly = t >> 4;          // /BW
        int lx = t & (BW - 1);
        float4 p0 = pts[ly][lx];
        float4 p1 = pts[ly][lx + 1];
        float4 p2 = pts[ly][lx + 2];
        float xx = fmaf(p2.x, p2.x, fmaf(p1.x, p1.x, p0.x * p0.x));
        float xy = fmaf(p2.x, p2.y, fmaf(p1.x, p1.y, p0.x * p0.y));
        float xz = fmaf(p2.x, p2.z, fmaf(p1.x, p1.z, p0.x * p0.z));
        float yy = fmaf(p2.y, p2.y, fmaf(p1.y, p1.y, p0.y * p0.y));
        float yz = fmaf(p2.y, p2.z, fmaf(p1.y, p1.z, p0.y * p0.z));
        float zz = fmaf(p2.z, p2.z, fmaf(p1.z, p1.z, p0.z * p0.z));
        float sx = __fadd_rn(__fadd_rn(p0.x, p1.x), p2.x);
        float sy = __fadd_rn(__fadd_rn(p0.y, p1.y), p2.y);
        float sz = __fadd_rn(__fadd_rn(p0.z, p1.z), p2.z);
        H1[ly][lx] = make_float4(xx, xy, xz, yy);
        H2[ly][lx] = make_float4(yz, zz, sx, sy);
        H3[ly][lx] = sz;
    }
    __syncthreads();

    // Phase C: two vertically-adjacent pixels per thread; 4 H-rows loaded
    // (windows overlap in rows r1, r2). Per-pixel additions keep R13's exact
    // left-to-right association -> bit-identical output.
    const int ty = threadIdx.y;
    const int tx = threadIdx.x;
    const int r0 = 2 * ty;

    float4 u0 = H1[r0][tx], u1 = H1[r0 + 1][tx];
    float4 u2 = H1[r0 + 2][tx], u3 = H1[r0 + 3][tx];
    float4 v0 = H2[r0][tx], v1 = H2[r0 + 1][tx];
    float4 v2 = H2[r0 + 2][tx], v3 = H2[r0 + 3][tx];
    float w0 = H3[r0][tx], w1 = H3[r0 + 1][tx];
    float w2 = H3[r0 + 2][tx], w3 = H3[r0 + 3][tx];

    // pixel 0: rows r0, r0+1, r0+2
    float o0a, o1a, o2a;
    solve_pixel(
        __fadd_rn(__fadd_rn(u0.x, u1.x), u2.x),
        __fadd_rn(__fadd_rn(u0.y, u1.y), u2.y),
        __fadd_rn(__fadd_rn(u0.z, u1.z), u2.z),
        __fadd_rn(__fadd_rn(u0.w, u1.w), u2.w),
        __fadd_rn(__fadd_rn(v0.x, v1.x), v2.x),
        __fadd_rn(__fadd_rn(v0.y, v1.y), v2.y),
        __fadd_rn(__fadd_rn(v0.z, v1.z), v2.z),
        __fadd_rn(__fadd_rn(v0.w, v1.w), v2.w),
        __fadd_rn(__fadd_rn(w0, w1), w2),
        r1x, r1y, r1z, b2x, b2y, b2z, b3x, b3y, b3z,
        o0a, o1a, o2a);

    // pixel 1: rows r0+1, r0+2, r0+3
    float o0b, o1b, o2b;
    solve_pixel(
        __fadd_rn(__fadd_rn(u1.x, u2.x), u3.x),
        __fadd_rn(__fadd_rn(u1.y, u2.y), u3.y),
        __fadd_rn(__fadd_rn(u1.z, u2.z), u3.z),
        __fadd_rn(__fadd_rn(u1.w, u2.w), u3.w),
        __fadd_rn(__fadd_rn(v1.x, v2.x), v3.x),
        __fadd_rn(__fadd_rn(v1.y, v2.y), v3.y),
        __fadd_rn(__fadd_rn(v1.z, v2.z), v3.z),
        __fadd_rn(__fadd_rn(v1.w, v2.w), v3.w),
        __fadd_rn(__fadd_rn(w1, w2), w3),
        r1x, r1y, r1z, b2x, b2y, b2z, b3x, b3y, b3z,
        o0b, o1b, o2b);

    const int gi = i0 + r0;
    const int gj = j0 + tx;
    size_t base = (size_t)bb * 3 * (HH * WW) + (size_t)gi * WW + gj;
    out[base]               = o0a;
    out[base +     HH * WW] = o1a;
    out[base + 2 * HH * WW] = o2a;
    base += WW;
    out[base]               = o0b;
    out[base +     HH * WW] = o1b;
    out[base + 2 * HH * WW] = o2b;
}

extern "C" void kernel_launch(void* const* d_in, const int* in_sizes, int n_in,
                              void* d_out, int out_size) {
    const float* depth = (const float*)d_in[0];
    float* out = (float*)d_out;

    rays_kernel<<<(WW + HH + 255) / 256, 256>>>();

    dim3 block(BW, TY, 1);
    dim3 grid(WW / BW, HH / TH, BATCH);
    normals_kernel<<<grid, block>>>(depth, out);
}

// round 16
// speedup vs baseline: 1.7719x; 1.0214x over previous
#include <cuda_runtime.h>
#include <math.h>

#define HH 512
#define WW 1024
#define BATCH 4
#define BW 16
#define TH 16
#define TY 8    // thread rows; each thread owns pixel rows 2*ty and 2*ty+1

// ---------------- ray tables (sin/cos in double, rounded to fp32) ----------
__device__ float g_st[WW];
__device__ float g_ct[WW];
__device__ float g_sp[HH];
__device__ float g_cp[HH];

// One output value per thread (sin and cos split) — same double-precision
// expressions as before, just computed in parallel -> bit-identical tables.
__global__ void rays_kernel() {
    int t = blockIdx.x * blockDim.x + threadIdx.x;
    const float PI_F = 3.14159265358979323846f;   // fl32(pi)
    if (t < 2 * WW) {
        int j = (t >= WW) ? t - WW : t;
        float jn = __fmul_rn((float)j + 0.5f, 1.0f / (float)WW);
        float th = __fsub_rn(__fmul_rn(jn, __fmul_rn(2.0f, PI_F)), PI_F);
        double thd = (double)th;
        if (t < WW) g_st[j] = (float)sin(thd);
        else        g_ct[j] = (float)cos(thd);
    } else if (t < 2 * WW + 2 * HH) {
        int u = t - 2 * WW;
        int i = (u >= HH) ? u - HH : u;
        float in_ = __fmul_rn((float)i + 0.5f, 1.0f / (float)HH);
        float ph = __fsub_rn(0.5f * PI_F, __fmul_rn(in_, PI_F));
        double phd = (double)ph;
        if (u < HH) g_sp[i] = (float)sin(phd);
        else        g_cp[i] = (float)cos(phd);
    }
}

// Kahan-compensated 2x2 determinant: a*b - c*d  (REQUIRED — R15 proved it)
__device__ __forceinline__ float det2(float a, float b, float c, float d) {
    float p = __fmul_rn(a, b);
    float e = fmaf(a, b, -p);
    float q = __fmul_rn(c, d);
    float f = fmaf(c, d, -q);
    return __fadd_rn(__fsub_rn(p, q), __fsub_rn(e, f));
}
// compensated a*x + b*y + c*z
__device__ __forceinline__ float dot3c(float a, float x, float b, float y,
                                       float c, float z) {
    float p0 = __fmul_rn(a, x), e0 = fmaf(a, x, -p0);
    float p1 = __fmul_rn(b, y), e1 = fmaf(b, y, -p1);
    float p2 = __fmul_rn(c, z), e2 = fmaf(c, z, -p2);
    float s  = __fadd_rn(p0, p1);
    float t  = __fsub_rn(s, p0);
    float er1 = __fadd_rn(__fsub_rn(p0, __fsub_rn(s, t)), __fsub_rn(p1, t));
    float s2 = __fadd_rn(s, p2);
    float t2 = __fsub_rn(s2, s);
    float er2 = __fadd_rn(__fsub_rn(s, __fsub_rn(s2, t2)), __fsub_rn(p2, t2));
    float lo = __fadd_rn(__fadd_rn(er1, er2), __fadd_rn(__fadd_rn(e0, e1), e2));
    return __fadd_rn(s2, lo);
}

// Full per-pixel solve in the rotated frame + rotate back + normalize.
__device__ __forceinline__ void solve_pixel(
    float ga, float gb, float gc, float gd, float ge, float gf,
    float bx, float by, float bz,
    float r1x, float r1y, float r1z,
    float b2x, float b2y, float b2z,
    float b3x, float b3y, float b3z,
    float& o0, float& o1, float& o2)
{
    ga = __fadd_rn(ga, 1e-5f);
    gd = __fadd_rn(gd, 1e-5f);
    gf = __fadd_rn(gf, 1e-5f);

    float A00 = det2(gd, gf, ge, ge);
    float A01 = det2(gc, ge, gb, gf);
    float A02 = det2(gb, ge, gc, gd);
    float A11 = det2(ga, gf, gc, gc);
    float A12 = det2(gb, gc, ga, ge);
    float A22 = det2(ga, gd, gb, gb);

    float m0 = dot3c(A00, bx, A01, by, A02, bz);
    float m1 = dot3c(A01, bx, A11, by, A12, bz);
    float m2 = dot3c(A02, bx, A12, by, A22, bz);

    float nx = fmaf(m0, r1x, fmaf(m1, b2x, m2 * b3x));
    float ny = fmaf(m0, r1y, fmaf(m1, b2y, m2 * b3y));
    float nz = fmaf(m0, r1z, fmaf(m1, b2z, m2 * b3z));

    float nn = fmaf(nx, nx, fmaf(ny, ny, nz * nz));
    float norm = sqrtf(nn);
    if (norm == 0.0f) norm = 1e-4f;
    o0 = __fdiv_rn(-nx, norm);
    o1 = __fdiv_rn(-ny, norm);
    o2 = __fdiv_rn(-nz, norm);
}

__global__ __launch_bounds__(BW * TY, 12)
void normals_kernel(const float* __restrict__ depth, float* __restrict__ out) {
    __shared__ float4 pts[TH + 2][BW + 2];  // rotated-frame points
    __shared__ float4 H1[TH + 2][BW];       // xx, xy, xz, yy
    __shared__ float4 H2[TH + 2][BW];       // yz, zz, bx, by
    __shared__ float  H3[TH + 2][BW];       // bz

    const int bb = blockIdx.z;
    const int i0 = blockIdx.y * TH;
    const int j0 = blockIdx.x * BW;
    const int tid = threadIdx.y * BW + threadIdx.x;
    const int NT = BW * TY;   // 128
    const float* dptr = depth + (size_t)bb * (HH * WW);

    // Per-block basis from the center pixel's ray.
    const int ic = i0 + TH / 2;
    const int jc = j0 + BW / 2;
    float r1x = g_cp[ic] * g_st[jc];
    float r1y = g_sp[ic];
    float r1z = g_cp[ic] * g_ct[jc];
    float ax, ay, az;
    if (fabsf(r1y) < 0.9f) { ax = 0.f; ay = 1.f; az = 0.f; }
    else                   { ax = 1.f; ay = 0.f; az = 0.f; }
    float b2x = r1y * az - r1z * ay;
    float b2y = r1z * ax - r1x * az;
    float b2z = r1x * ay - r1y * ax;
    float inv2 = rsqrtf(b2x * b2x + b2y * b2y + b2z * b2z);
    b2x *= inv2; b2y *= inv2; b2z *= inv2;
    float b3x = r1y * b2z - r1z * b2y;
    float b3y = r1z * b2x - r1x * b2z;
    float b3z = r1x * b2y - r1y * b2x;

    // Phase A: rotated fp32 point tile, zero-padded.
#pragma unroll
    for (int t = tid; t < (TH + 2) * (BW + 2); t += NT) {
        int ly = t / (BW + 2);
        int lx = t - ly * (BW + 2);
        int gi = i0 + ly - 1;
        int gj = j0 + lx - 1;
        float4 q = make_float4(0.f, 0.f, 0.f, 0.f);
        if (gi >= 0 && gi < HH && gj >= 0 && gj < WW) {
            float d  = __ldg(&dptr[(size_t)gi * WW + gj]);
            float st = g_st[gj];
            float ct = g_ct[gj];
            float sp = g_sp[gi];
            float cp = g_cp[gi];
            float px = __fmul_rn(d, __fmul_rn(cp, st));
            float py = __fmul_rn(d, sp);
            float pz = __fmul_rn(d, __fmul_rn(cp, ct));
            q.x = fmaf(r1x, px, fmaf(r1y, py, r1z * pz));
            q.y = fmaf(b2x, px, fmaf(b2y, py, b2z * pz));
            q.z = fmaf(b3x, px, fmaf(b3y, py, b3z * pz));
        }
        pts[ly][lx] = q;
    }
    __syncthreads();

    // Phase B: horizontal 3-window sums, plain fp32.
#pragma unroll
    for (int t = tid; t < (TH + 2) * BW; t += NT) {
        int ly = t >> 4;          // /BW
        int lx = t & (BW - 1);
        float4 p0 = pts[ly][lx];
        float4 p1 = pts[ly][lx + 1];
        float4 p2 = pts[ly][lx + 2];
        float xx = fmaf(p2.x, p2.x, fmaf(p1.x, p1.x, p0.x * p0.x));
        float xy = fmaf(p2.x, p2.y, fmaf(p1.x, p1.y, p0.x * p0.y));
        float xz = fmaf(p2.x, p2.z, fmaf(p1.x, p1.z, p0.x * p0.z));
        float yy = fmaf(p2.y, p2.y, fmaf(p1.y, p1.y, p0.y * p0.y));
        float yz = fmaf(p2.y, p2.z, fmaf(p1.y, p1.z, p0.y * p0.z));
        float zz = fmaf(p2.z, p2.z, fmaf(p1.z, p1.z, p0.z * p0.z));
        float sx = __fadd_rn(__fadd_rn(p0.x, p1.x), p2.x);
        float sy = __fadd_rn(__fadd_rn(p0.y, p1.y), p2.y);
        float sz = __fadd_rn(__fadd_rn(p0.z, p1.z), p2.z);
        H1[ly][lx] = make_float4(xx, xy, xz, yy);
        H2[ly][lx] = make_float4(yz, zz, sx, sy);
        H3[ly][lx] = sz;
    }
    __syncthreads();

    // Phase C: two vertically-adjacent pixels per thread; 4 H-rows loaded.
    const int ty = threadIdx.y;
    const int tx = threadIdx.x;
    const int r0 = 2 * ty;

    float4 u0 = H1[r0][tx], u1 = H1[r0 + 1][tx];
    float4 u2 = H1[r0 + 2][tx], u3 = H1[r0 + 3][tx];
    float4 v0 = H2[r0][tx], v1 = H2[r0 + 1][tx];
    float4 v2 = H2[r0 + 2][tx], v3 = H2[r0 + 3][tx];
    float w0 = H3[r0][tx], w1 = H3[r0 + 1][tx];
    float w2 = H3[r0 + 2][tx], w3 = H3[r0 + 3][tx];

    // pixel 0: rows r0, r0+1, r0+2
    float o0a, o1a, o2a;
    solve_pixel(
        __fadd_rn(__fadd_rn(u0.x, u1.x), u2.x),
        __fadd_rn(__fadd_rn(u0.y, u1.y), u2.y),
        __fadd_rn(__fadd_rn(u0.z, u1.z), u2.z),
        __fadd_rn(__fadd_rn(u0.w, u1.w), u2.w),
        __fadd_rn(__fadd_rn(v0.x, v1.x), v2.x),
        __fadd_rn(__fadd_rn(v0.y, v1.y), v2.y),
        __fadd_rn(__fadd_rn(v0.z, v1.z), v2.z),
        __fadd_rn(__fadd_rn(v0.w, v1.w), v2.w),
        __fadd_rn(__fadd_rn(w0, w1), w2),
        r1x, r1y, r1z, b2x, b2y, b2z, b3x, b3y, b3z,
        o0a, o1a, o2a);

    // pixel 1: rows r0+1, r0+2, r0+3
    float o0b, o1b, o2b;
    solve_pixel(
        __fadd_rn(__fadd_rn(u1.x, u2.x), u3.x),
        __fadd_rn(__fadd_rn(u1.y, u2.y), u3.y),
        __fadd_rn(__fadd_rn(u1.z, u2.z), u3.z),
        __fadd_rn(__fadd_rn(u1.w, u2.w), u3.w),
        __fadd_rn(__fadd_rn(v1.x, v2.x), v3.x),
        __fadd_rn(__fadd_rn(v1.y, v2.y), v3.y),
        __fadd_rn(__fadd_rn(v1.z, v2.z), v3.z),
        __fadd_rn(__fadd_rn(v1.w, v2.w), v3.w),
        __fadd_rn(__fadd_rn(w1, w2), w3),
        r1x, r1y, r1z, b2x, b2y, b2z, b3x, b3y, b3z,
        o0b, o1b, o2b);

    const int gi = i0 + r0;
    const int gj = j0 + tx;
    size_t base = (size_t)bb * 3 * (HH * WW) + (size_t)gi * WW + gj;
    out[base]               = o0a;
    out[base +     HH * WW] = o1a;
    out[base + 2 * HH * WW] = o2a;
    base += WW;
    out[base]               = o0b;
    out[base +     HH * WW] = o1b;
    out[base + 2 * HH * WW] = o2b;
}

extern "C" void kernel_launch(void* const* d_in, const int* in_sizes, int n_in,
                              void* d_out, int out_size) {
    const float* depth = (const float*)d_in[0];
    float* out = (float*)d_out;

    rays_kernel<<<(2 * (WW + HH) + 255) / 256, 256>>>();

    dim3 block(BW, TY, 1);
    dim3 grid(WW / BW, HH / TH, BATCH);
    normals_kernel<<<grid, block>>>(depth, out);
}